// round 7
// baseline (speedup 1.0000x reference)
#include <cuda_runtime.h>

#define BB 16
#define SS 4096
#define HH 16
#define EE 64
#define SDIM 64
#define NW 127

// Scratch (device globals — no allocation allowed in kernel_launch)
__device__ float g_vs4[4*BB*HH*SDIM*EE]; // [q][b][h][j][e] partial column sums
__device__ float g_us[BB*HH*SDIM*EE];    // [b][h][i][e]    row sums (complete)
__device__ float g_rv[BB*SDIM*HH*EE];    // [b][k][h][e]    RxV
__device__ float g_ru[BB*SDIM*HH*EE];    // [b][k][h][e]    RxU
__device__ float g_zc[HH*SDIM];          // [h][k]          z conv (x64)
__device__ int   g_cnt_reduce[BB];       // 64 arrivals per batch
__device__ int   g_cnt_conv[BB];         // 32 arrivals per batch

struct SRed  { float4 stage[2][8*8*16]; };                       // 32KB
struct SConv { float vs[SDIM*EE]; float us[SDIM*EE];
               float w[NW+1]; float o[SDIM]; };                  // ~32.8KB
struct SZ    { float zc[HH*SDIM]; };

union SMem { SRed r; SConv c; SZ z; };

__global__ void k_zero() {
    int t = threadIdx.x;
    if (t < BB) { g_cnt_reduce[t] = 0; g_cnt_conv[t] = 0; }
}

__device__ __forceinline__ void wait_cnt(int* p, int target, int t) {
    if (t == 0) {
        while (*(volatile int*)p < target) __nanosleep(128);
    }
    __syncthreads();
}

__device__ __forceinline__ void signal_cnt(int* p, int t) {
    __threadfence();
    __syncthreads();
    if (t == 0) atomicAdd(p, 1);
}

// ---------------------------------------------------------------------------
// Fused persistent-dataflow kernel.
// Roles by blockIdx.x:
//   [0,1024)     reduce: quarter-plane row/col sums of v.
//                4 blocks per (b,h) -> 64 blocks per batch.
//   [1024,1536)  conv:   64-tap circular convs (32 blocks/batch), waits for
//                its batch's 64 reduce arrivals.
//   [1536,2560)  out:    pbv broadcast-add + 256MB write, waits conv (32).
//   [2560,2576)  z:      z_pb output, waits conv of b=0.
// Block-id order puts every producer before its consumers, so in-order
// dispatch can never deadlock; consumers spin with nanosleep. While late
// batches' reduce blocks still stream v (reads), early batches' out blocks
// already stream pbv (writes) -> read/write overlap, no kernel boundaries.
// ---------------------------------------------------------------------------
__global__ __launch_bounds__(256) void k_fused(const float* __restrict__ v,
                                               const float* __restrict__ w,
                                               const float* __restrict__ o_,
                                               float* __restrict__ out) {
    __shared__ SMem sm;
    int bid = blockIdx.x;
    int t = threadIdx.x;

    if (bid < 1024) {
        // ----- reduce role: (bh, q) quarter = 16 i-rows -----
        int bh = bid >> 2, q = bid & 3;          // bh in [0,256)
        int b = bh >> 4, h = bh & 15;
        int e4 = t & 15, sub = (t >> 4) & 1, wpw = t >> 5;   // 8 warps

        const float4* v4 = reinterpret_cast<const float4*>(v)
                         + (size_t)b*SS*(HH*EE/4) + h*(EE/4) + e4;

        int i = q*16 + wpw*2 + sub;      // this thread's i-row
        float4 crow = make_float4(0.f,0.f,0.f,0.f);

        float* vs_dst = g_vs4 + (size_t)(q*BB*HH + bh)*SDIM*EE;

        #pragma unroll 1
        for (int jc = 0; jc < 8; ++jc) {
            float4 vloc[8];
            const float4* p0 = v4 + (size_t)(i*SDIM + jc*8)*(HH*EE/4);
            #pragma unroll
            for (int jj = 0; jj < 8; ++jj) {
                float4 a = __ldcs(p0 + (size_t)jj*(HH*EE/4));
                crow.x += a.x; crow.y += a.y; crow.z += a.z; crow.w += a.w;
                vloc[jj] = a;
            }
            // combine the warp's two i-rows (sub 0/1) for the column sums
            #pragma unroll
            for (int jj = 0; jj < 8; ++jj) {
                vloc[jj].x += __shfl_down_sync(0xffffffffu, vloc[jj].x, 16);
                vloc[jj].y += __shfl_down_sync(0xffffffffu, vloc[jj].y, 16);
                vloc[jj].z += __shfl_down_sync(0xffffffffu, vloc[jj].z, 16);
                vloc[jj].w += __shfl_down_sync(0xffffffffu, vloc[jj].w, 16);
            }
            if (sub == 0) {
                #pragma unroll
                for (int jj = 0; jj < 8; ++jj)
                    sm.r.stage[jc & 1][(wpw*8 + jj)*16 + e4] = vloc[jj];
            }
            __syncthreads();

            // alternate halves: the other half proceeds to next chunk's loads
            bool lower = (t < 128);
            if (lower == ((jc & 1) == 0)) {
                int tt = t & 127;
                int jj = tt >> 4, ee = tt & 15;
                float4 s = sm.r.stage[jc & 1][jj*16 + ee];
                #pragma unroll
                for (int ww = 1; ww < 8; ++ww) {
                    float4 x = sm.r.stage[jc & 1][(ww*8 + jj)*16 + ee];
                    s.x += x.x; s.y += x.y; s.z += x.z; s.w += x.w;
                }
                reinterpret_cast<float4*>(vs_dst + (jc*8 + jj)*EE)[ee] = s;
            }
        }

        // row sums (complete for this thread's i)
        float4* us4 = reinterpret_cast<float4*>(g_us + (size_t)bh*SDIM*EE);
        us4[i*(EE/4) + e4] = crow;

        signal_cnt(&g_cnt_reduce[b], t);

    } else if (bid < 1536) {
        // ----- conv role: (bh, kh) half-k -----
        int blk = bid - 1024;
        int bh = blk >> 1, kh = blk & 1;
        int b = bh >> 4, h = bh & 15;

        if (t < NW) sm.c.w[t] = w[h*NW + t];
        if (t >= 128 && t < 128 + SDIM) sm.c.o[t - 128] = o_[t - 128];

        wait_cnt(&g_cnt_reduce[b], 64, t);

        const size_t base = (size_t)bh*SDIM*EE;
        const size_t slice = (size_t)BB*HH*SDIM*EE;
        {
            const float4* p0 = reinterpret_cast<const float4*>(g_vs4 + base);
            const float4* pu = reinterpret_cast<const float4*>(g_us + base);
            float4* vsv = reinterpret_cast<float4*>(sm.c.vs);
            float4* usv = reinterpret_cast<float4*>(sm.c.us);
            #pragma unroll
            for (int r = 0; r < 4; ++r) {
                int idx = r*256 + t;
                float4 a = __ldcg(p0 + idx);
                float4 x = __ldcg(p0 + slice/4 + idx);
                float4 y = __ldcg(p0 + 2*(slice/4) + idx);
                float4 zz = __ldcg(p0 + 3*(slice/4) + idx);
                vsv[idx] = make_float4(a.x+x.x+y.x+zz.x, a.y+x.y+y.y+zz.y,
                                       a.z+x.z+y.z+zz.z, a.w+x.w+y.w+zz.w);
                usv[idx] = __ldcg(pu + idx);
            }
        }
        __syncthreads();

        if (b == 0 && kh == 0 && t < SDIM) {
            float acc = 0.f;
            #pragma unroll
            for (int j = 0; j < SDIM; ++j) {
                int idx = t + 64 - j;
                if (idx > 126) idx -= 127;
                acc += sm.c.o[j] * sm.c.w[idx];
            }
            g_zc[h*SDIM + t] = acc * 64.f;
        }

        int e = t & 63, g = t >> 6;
        #pragma unroll 1
        for (int k = kh*32 + g; k < kh*32 + 32; k += 4) {
            float rv = 0.f, ru = 0.f;
            #pragma unroll
            for (int j = 0; j < SDIM; ++j) {
                int idx = k + 64 - j;            // [1,127]
                if (idx > 126) idx -= 127;
                float wk = sm.c.w[idx];
                rv += sm.c.vs[j*EE + e] * wk;
                ru += sm.c.us[j*EE + e] * wk;
            }
            size_t o = ((size_t)(b*SDIM + k)*HH + h)*EE + e;
            g_rv[o] = rv;
            g_ru[o] = ru;
        }

        signal_cnt(&g_cnt_conv[b], t);

    } else if (bid < 2560) {
        // ----- out role: 8i x 8j tile of pbv -----
        int blk = bid - 1536;
        int b = blk >> 6;
        int itile = (blk >> 3) & 7;
        int jt = blk & 7;

        wait_cnt(&g_cnt_conv[b], 32, t);

        const float4* rub = reinterpret_cast<const float4*>(g_ru + (size_t)b*SDIM*HH*EE);
        const float4* rvb = reinterpret_cast<const float4*>(g_rv + (size_t)b*SDIM*HH*EE);
        float4* ob = reinterpret_cast<float4*>(out + (size_t)b*SS*HH*EE);

        float4 uu[8];
        #pragma unroll
        for (int m = 0; m < 8; ++m)
            uu[m] = __ldcg(rub + (itile*8 + m)*(HH*EE/4) + t);

        #pragma unroll
        for (int jj = 0; jj < 8; ++jj) {
            int j = jt*8 + jj;
            float4 vv = __ldcg(rvb + j*(HH*EE/4) + t);
            #pragma unroll
            for (int m = 0; m < 8; ++m) {
                int i = itile*8 + m;
                float4 o;
                o.x = vv.x + uu[m].x; o.y = vv.y + uu[m].y;
                o.z = vv.z + uu[m].z; o.w = vv.w + uu[m].w;
                __stcs(ob + ((size_t)i*SDIM + j)*(HH*EE/4) + t, o);
            }
        }

    } else {
        // ----- z role: z_pb output from g_zc -----
        int zi = bid - 2560;            // 0..15 -> i = zi*4 .. +3
        wait_cnt(&g_cnt_conv[0], 32, t);

        for (int idx = t; idx < HH*SDIM; idx += 256)
            sm.z.zc[idx] = __ldcg((const float*)g_zc + idx);
        __syncthreads();

        float* o2 = out + (size_t)BB*SS*HH*EE;
        #pragma unroll
        for (int r = 0; r < 4; ++r) {
            int i = zi*4 + r;
            #pragma unroll
            for (int it = 0; it < 4; ++it) {
                int idx = it*256 + t;
                int j = idx >> 4, h = idx & 15;
                o2[(size_t)i*1024 + idx] = sm.z.zc[h*SDIM + j] + sm.z.zc[h*SDIM + i];
            }
        }
    }
}

extern "C" void kernel_launch(void* const* d_in, const int* in_sizes, int n_in,
                              void* d_out, int out_size) {
    const float* v  = (const float*)d_in[0];
    const float* w  = (const float*)d_in[1];
    const float* o_ = (const float*)d_in[2];
    float* out = (float*)d_out;

    k_zero <<<1, 32>>>();
    k_fused<<<2576, 256>>>(v, w, o_, out);
}

// round 8
// speedup vs baseline: 1.1485x; 1.1485x over previous
#include <cuda_runtime.h>

#define BB 16
#define SS 4096
#define HH 16
#define EE 64
#define SDIM 64
#define NW 127

// Scratch (device globals — no allocation allowed in kernel_launch)
__device__ float g_vs4[4*BB*HH*SDIM*EE]; // [q][b][h][j][e] partial column sums
__device__ float g_us[BB*HH*SDIM*EE];    // [b][h][i][e]    row sums (complete)
__device__ float g_rv[BB*SDIM*HH*EE];    // [b][k][h][e]    RxV
__device__ float g_ru[BB*SDIM*HH*EE];    // [b][k][h][e]    RxU
__device__ float g_zc[HH*SDIM];          // [h][k]          z conv (x64)
__device__ int   g_cnt_reduce[BB];       // 64 arrivals per batch
__device__ int   g_cnt_conv[BB];         // 32 arrivals per batch

struct SRed  { float4 stage[2][8*8*16]; };                       // 32KB
struct SConv { float vs[SDIM*EE]; float us[SDIM*EE];
               float w[NW+1]; float o[SDIM]; };                  // ~32.8KB
struct SZ    { float zc[HH*SDIM]; };

union SMem { SRed r; SConv c; SZ z; };

__global__ void k_zero() {
    int t = threadIdx.x;
    if (t < BB) { g_cnt_reduce[t] = 0; g_cnt_conv[t] = 0; }
}

__device__ __forceinline__ void wait_cnt(int* p, int target, int t) {
    if (t == 0) {
        while (*(volatile int*)p < target) __nanosleep(128);
    }
    __syncthreads();
}

__device__ __forceinline__ void signal_cnt(int* p, int t) {
    __threadfence();
    __syncthreads();
    if (t == 0) atomicAdd(p, 1);
}

// ---------------------------------------------------------------------------
// Fused persistent-dataflow kernel, register-capped to 64/thread so each SM
// holds 4 blocks (the residency the standalone reduce kernel ran at).
// Roles by blockIdx.x:
//   [0,1024)     reduce: quarter-plane row/col sums of v (64 blocks/batch)
//   [1024,1536)  conv:   circular convs (32 blocks/batch), waits reduce=64
//   [1536,2560)  out:    pbv broadcast-add + 256MB write, waits conv=32
//   [2560,2576)  z:      z_pb output, waits conv of b=0
// Producers precede consumers in block-id order -> no dispatch deadlock.
// ---------------------------------------------------------------------------
__global__ __launch_bounds__(256, 4) void k_fused(const float* __restrict__ v,
                                                  const float* __restrict__ w,
                                                  const float* __restrict__ o_,
                                                  float* __restrict__ out) {
    __shared__ SMem sm;
    int bid = blockIdx.x;
    int t = threadIdx.x;

    if (bid < 1024) {
        // ----- reduce role: (bh, q) quarter = 16 i-rows -----
        int bh = bid >> 2, q = bid & 3;          // bh in [0,256)
        int b = bh >> 4, h = bh & 15;
        int e4 = t & 15, sub = (t >> 4) & 1, wpw = t >> 5;   // 8 warps

        const float4* v4 = reinterpret_cast<const float4*>(v)
                         + (size_t)b*SS*(HH*EE/4) + h*(EE/4) + e4;

        int i = q*16 + wpw*2 + sub;      // this thread's i-row
        float4 crow = make_float4(0.f,0.f,0.f,0.f);

        float* vs_dst = g_vs4 + (size_t)(q*BB*HH + bh)*SDIM*EE;

        #pragma unroll 1
        for (int jc = 0; jc < 8; ++jc) {
            float4 vloc[8];
            const float4* p0 = v4 + (size_t)(i*SDIM + jc*8)*(HH*EE/4);
            #pragma unroll
            for (int jj = 0; jj < 8; ++jj) {
                float4 a = __ldcs(p0 + (size_t)jj*(HH*EE/4));
                crow.x += a.x; crow.y += a.y; crow.z += a.z; crow.w += a.w;
                vloc[jj] = a;
            }
            // combine the warp's two i-rows (sub 0/1) for the column sums
            #pragma unroll
            for (int jj = 0; jj < 8; ++jj) {
                vloc[jj].x += __shfl_down_sync(0xffffffffu, vloc[jj].x, 16);
                vloc[jj].y += __shfl_down_sync(0xffffffffu, vloc[jj].y, 16);
                vloc[jj].z += __shfl_down_sync(0xffffffffu, vloc[jj].z, 16);
                vloc[jj].w += __shfl_down_sync(0xffffffffu, vloc[jj].w, 16);
            }
            if (sub == 0) {
                #pragma unroll
                for (int jj = 0; jj < 8; ++jj)
                    sm.r.stage[jc & 1][(wpw*8 + jj)*16 + e4] = vloc[jj];
            }
            __syncthreads();

            // alternate halves: the other half proceeds to next chunk's loads
            bool lower = (t < 128);
            if (lower == ((jc & 1) == 0)) {
                int tt = t & 127;
                int jj = tt >> 4, ee = tt & 15;
                float4 s = sm.r.stage[jc & 1][jj*16 + ee];
                #pragma unroll
                for (int ww = 1; ww < 8; ++ww) {
                    float4 x = sm.r.stage[jc & 1][(ww*8 + jj)*16 + ee];
                    s.x += x.x; s.y += x.y; s.z += x.z; s.w += x.w;
                }
                reinterpret_cast<float4*>(vs_dst + (jc*8 + jj)*EE)[ee] = s;
            }
        }

        // row sums (complete for this thread's i)
        float4* us4 = reinterpret_cast<float4*>(g_us + (size_t)bh*SDIM*EE);
        us4[i*(EE/4) + e4] = crow;

        signal_cnt(&g_cnt_reduce[b], t);

    } else if (bid < 1536) {
        // ----- conv role: (bh, kh) half-k -----
        int blk = bid - 1024;
        int bh = blk >> 1, kh = blk & 1;
        int b = bh >> 4, h = bh & 15;

        if (t < NW) sm.c.w[t] = w[h*NW + t];
        if (t >= 128 && t < 128 + SDIM) sm.c.o[t - 128] = o_[t - 128];

        wait_cnt(&g_cnt_reduce[b], 64, t);

        const size_t base = (size_t)bh*SDIM*EE;
        const size_t slice4 = (size_t)BB*HH*SDIM*EE/4;
        {
            const float4* p0 = reinterpret_cast<const float4*>(g_vs4 + base);
            const float4* pu = reinterpret_cast<const float4*>(g_us + base);
            float4* vsv = reinterpret_cast<float4*>(sm.c.vs);
            float4* usv = reinterpret_cast<float4*>(sm.c.us);
            #pragma unroll
            for (int r = 0; r < 4; ++r) {
                int idx = r*256 + t;
                float4 a = __ldcg(p0 + idx);
                float4 x = __ldcg(p0 + slice4 + idx);
                float4 y = __ldcg(p0 + 2*slice4 + idx);
                float4 zz = __ldcg(p0 + 3*slice4 + idx);
                vsv[idx] = make_float4(a.x+x.x+y.x+zz.x, a.y+x.y+y.y+zz.y,
                                       a.z+x.z+y.z+zz.z, a.w+x.w+y.w+zz.w);
                usv[idx] = __ldcg(pu + idx);
            }
        }
        __syncthreads();

        if (b == 0 && kh == 0 && t < SDIM) {
            float acc = 0.f;
            #pragma unroll
            for (int j = 0; j < SDIM; ++j) {
                int idx = t + 64 - j;
                if (idx > 126) idx -= 127;
                acc += sm.c.o[j] * sm.c.w[idx];
            }
            g_zc[h*SDIM + t] = acc * 64.f;
        }

        int e = t & 63, g = t >> 6;
        #pragma unroll 1
        for (int k = kh*32 + g; k < kh*32 + 32; k += 4) {
            float rv = 0.f, ru = 0.f;
            #pragma unroll
            for (int j = 0; j < SDIM; ++j) {
                int idx = k + 64 - j;            // [1,127]
                if (idx > 126) idx -= 127;
                float wk = sm.c.w[idx];
                rv += sm.c.vs[j*EE + e] * wk;
                ru += sm.c.us[j*EE + e] * wk;
            }
            size_t o = ((size_t)(b*SDIM + k)*HH + h)*EE + e;
            g_rv[o] = rv;
            g_ru[o] = ru;
        }

        signal_cnt(&g_cnt_conv[b], t);

    } else if (bid < 2560) {
        // ----- out role: 8i x 8j tile of pbv -----
        int blk = bid - 1536;
        int b = blk >> 6;
        int itile = (blk >> 3) & 7;
        int jt = blk & 7;

        wait_cnt(&g_cnt_conv[b], 32, t);

        const float4* rub = reinterpret_cast<const float4*>(g_ru + (size_t)b*SDIM*HH*EE)
                          + (size_t)itile*8*(HH*EE/4) + t;
        const float4* rvb = reinterpret_cast<const float4*>(g_rv + (size_t)b*SDIM*HH*EE)
                          + (size_t)jt*8*(HH*EE/4) + t;
        float4* ob = reinterpret_cast<float4*>(out + (size_t)b*SS*HH*EE)
                   + ((size_t)itile*8*SDIM + jt*8)*(HH*EE/4) + t;

        float4 uu[8];
        #pragma unroll
        for (int m = 0; m < 8; ++m)
            uu[m] = __ldcg(rub + m*(HH*EE/4));

        #pragma unroll 1
        for (int jj = 0; jj < 8; ++jj) {
            float4 vv = __ldcg(rvb + jj*(HH*EE/4));
            #pragma unroll
            for (int m = 0; m < 8; ++m) {
                float4 o;
                o.x = vv.x + uu[m].x; o.y = vv.y + uu[m].y;
                o.z = vv.z + uu[m].z; o.w = vv.w + uu[m].w;
                __stcs(ob + ((size_t)m*SDIM + jj)*(HH*EE/4), o);
            }
        }

    } else {
        // ----- z role: z_pb output from g_zc -----
        int zi = bid - 2560;            // 0..15 -> i = zi*4 .. +3
        wait_cnt(&g_cnt_conv[0], 32, t);

        for (int idx = t; idx < HH*SDIM; idx += 256)
            sm.z.zc[idx] = __ldcg((const float*)g_zc + idx);
        __syncthreads();

        float* o2 = out + (size_t)BB*SS*HH*EE;
        #pragma unroll
        for (int r = 0; r < 4; ++r) {
            int i = zi*4 + r;
            #pragma unroll
            for (int it = 0; it < 4; ++it) {
                int idx = it*256 + t;
                int j = idx >> 4, h = idx & 15;
                o2[(size_t)i*1024 + idx] = sm.z.zc[h*SDIM + j] + sm.z.zc[h*SDIM + i];
            }
        }
    }
}

extern "C" void kernel_launch(void* const* d_in, const int* in_sizes, int n_in,
                              void* d_out, int out_size) {
    const float* v  = (const float*)d_in[0];
    const float* w  = (const float*)d_in[1];
    const float* o_ = (const float*)d_in[2];
    float* out = (float*)d_out;

    k_zero <<<1, 32>>>();
    k_fused<<<2576, 256>>>(v, w, o_, out);
}